// round 2
// baseline (speedup 1.0000x reference)
#include <cuda_runtime.h>
#include <math.h>

// ---------------- problem constants ----------------
#define E_  4
#define N_  2048
#define D_  512
#define M_  2048
#define L_  3
#define F_  2048
#define EN_ (E_*N_)            // 8192
#define ND_ (N_*D_)            // 1048576
#define NM_ (N_*M_)            // 4194304
#define DD_ (D_*D_)            // 262144

// ---------------- scratch (static device arrays; no allocation) -------------
// g_big serves three non-overlapping phases:
//   phase A: cross-attention logits [8192 x 8192]          (256 MB)
//   phase B: per-expert attn scores [8][2048][2048] (reuse front 128 MB)
//   phase B': ffn hidden h1 [E][N][F] aliased at front     (64 MB)  -- after scores dead
//   phase C: memory attention [E][L][N][M]                 (192 MB)
__device__ float g_ln_tok[EN_*D_];
__device__ float g_cross [EN_*D_];
__device__ float g_big   [EN_*EN_];
__device__ float g_q     [EN_*D_];
__device__ float g_k     [EN_*D_];
__device__ float g_v     [EN_*D_];
__device__ float g_ao    [EN_*D_];
__device__ float g_eo    [EN_*D_];
__device__ float g_retr  [E_*N_*L_*D_];
__device__ float g_outb  [EN_*D_];
__device__ float g_upd   [L_*M_*D_];
__device__ float g_pool  [E_*D_];
__device__ float g_gate  [E_];

// ---------------- generic tiled SGEMM with epilogues ----------------
// C[m,n] = epi( alpha * sum_k opA(A)[m,k]*opB(B)[k,n] )
// EPI: 0 none | 1 clip10+blockmask | 2 clip10 | 3 +bias | 4 relu(+bias)
//      5 +bias?+addend | 6 C += clip(v,-1,1)
// BOUND: emit M/N bounds checks (only needed when M or N not multiple of 128)
template<int EPI, bool TA, bool TB, bool BOUND>
__global__ __launch_bounds__(256)
void gemm_k(int M, int N, int K, float alpha,
            const float* __restrict__ A, int lda, size_t sA,
            const float* __restrict__ B, int ldb, size_t sB,
            float* __restrict__ C, int ldc, size_t sC,
            const float* __restrict__ bias, size_t sBias,
            const float* __restrict__ addend, size_t sAdd,
            int maskDiv)
{
    int z = blockIdx.z;
    A += (size_t)z * sA;
    B += (size_t)z * sB;
    C += (size_t)z * sC;
    if (bias)   bias   += (size_t)z * sBias;
    if (addend) addend += (size_t)z * sAdd;

    const int m0 = blockIdx.y * 128;
    const int n0 = blockIdx.x * 128;

    __shared__ float As[16][132];
    __shared__ float Bs[16][132];

    const int tid = threadIdx.x;
    const int tx = tid & 15;      // n direction
    const int ty = tid >> 4;      // m direction

    float acc[8][8];
#pragma unroll
    for (int i = 0; i < 8; i++)
#pragma unroll
        for (int j = 0; j < 8; j++) acc[i][j] = 0.f;

    for (int k0 = 0; k0 < K; k0 += 16) {
#pragma unroll
        for (int r = 0; r < 8; r++) {
            int idx = tid + r * 256;
            int m, k;
            if (TA) { k = idx >> 7; m = idx & 127; }
            else    { m = idx >> 4; k = idx & 15; }
            int gm = m0 + m, gk = k0 + k;
            float val = 0.f;
            if (!BOUND || gm < M)
                val = TA ? A[(size_t)gk * lda + gm] : A[(size_t)gm * lda + gk];
            As[k][m] = val;
        }
#pragma unroll
        for (int r = 0; r < 8; r++) {
            int idx = tid + r * 256;
            int k, n;
            if (TB) { n = idx >> 4; k = idx & 15; }
            else    { k = idx >> 7; n = idx & 127; }
            int gn = n0 + n, gk = k0 + k;
            float val = 0.f;
            if (!BOUND || gn < N)
                val = TB ? B[(size_t)gn * ldb + gk] : B[(size_t)gk * ldb + gn];
            Bs[k][n] = val;
        }
        __syncthreads();
#pragma unroll
        for (int k = 0; k < 16; k++) {
            float4 a0 = *(const float4*)&As[k][ty * 8];
            float4 a1 = *(const float4*)&As[k][ty * 8 + 4];
            float4 b0 = *(const float4*)&Bs[k][tx * 8];
            float4 b1 = *(const float4*)&Bs[k][tx * 8 + 4];
            float a[8] = {a0.x,a0.y,a0.z,a0.w,a1.x,a1.y,a1.z,a1.w};
            float b[8] = {b0.x,b0.y,b0.z,b0.w,b1.x,b1.y,b1.z,b1.w};
#pragma unroll
            for (int i = 0; i < 8; i++)
#pragma unroll
                for (int j = 0; j < 8; j++)
                    acc[i][j] += a[i] * b[j];
        }
        __syncthreads();
    }

#pragma unroll
    for (int i = 0; i < 8; i++) {
        int gm = m0 + ty * 8 + i;
        if (BOUND && gm >= M) continue;
#pragma unroll
        for (int j = 0; j < 8; j++) {
            int gn = n0 + tx * 8 + j;
            if (BOUND && gn >= N) continue;
            float v = alpha * acc[i][j];
            size_t ci = (size_t)gm * ldc + gn;
            if (EPI == 1) {
                v = fminf(fmaxf(v, -10.f), 10.f);
                if (gm / maskDiv == gn / maskDiv) v = -INFINITY;
                C[ci] = v;
            } else if (EPI == 2) {
                C[ci] = fminf(fmaxf(v, -10.f), 10.f);
            } else if (EPI == 3) {
                C[ci] = v + bias[gn];
            } else if (EPI == 4) {
                C[ci] = fmaxf(v + bias[gn], 0.f);
            } else if (EPI == 5) {
                if (bias) v += bias[gn];
                C[ci] = v + addend[ci];
            } else if (EPI == 6) {
                C[ci] += fminf(fmaxf(v, -1.f), 1.f);
            } else {
                C[ci] = v;
            }
        }
    }
}

// ---------------- layernorm (row length 512, 128 threads/block) -------------
__global__ void ln_kernel(const float* __restrict__ x, float* __restrict__ y)
{
    int row = blockIdx.x, t = threadIdx.x;
    const float4* xr = (const float4*)(x + (size_t)row * 512);
    float4 v = xr[t];
    float s = v.x + v.y + v.z + v.w;
    float q = v.x*v.x + v.y*v.y + v.z*v.z + v.w*v.w;
#pragma unroll
    for (int o = 16; o; o >>= 1) {
        s += __shfl_xor_sync(0xffffffffu, s, o);
        q += __shfl_xor_sync(0xffffffffu, q, o);
    }
    __shared__ float ss[4], sq[4];
    int w = t >> 5;
    if ((t & 31) == 0) { ss[w] = s; sq[w] = q; }
    __syncthreads();
    s = ss[0] + ss[1] + ss[2] + ss[3];
    q = sq[0] + sq[1] + sq[2] + sq[3];
    float mean = s * (1.f / 512.f);
    float var  = q * (1.f / 512.f) - mean * mean;
    float inv  = rsqrtf(var + 1e-5f);
    float4 o4;
    o4.x = (v.x - mean) * inv;
    o4.y = (v.y - mean) * inv;
    o4.z = (v.z - mean) * inv;
    o4.w = (v.w - mean) * inv;
    ((float4*)(y + (size_t)row * 512))[t] = o4;
}

// y = LN(a + b) * gamma + beta   (per-expert affine; which selects LN index)
__global__ void addln_kernel(const float* __restrict__ a, const float* __restrict__ b,
                             const float* __restrict__ gamma, const float* __restrict__ beta,
                             float* __restrict__ y, int which)
{
    int row = blockIdx.x, t = threadIdx.x;
    int e = row >> 11;
    const float4* ar = (const float4*)(a + (size_t)row * 512);
    const float4* br = (const float4*)(b + (size_t)row * 512);
    const float4* gr = (const float4*)(gamma + ((size_t)e * 2 + which) * 512);
    const float4* be = (const float4*)(beta  + ((size_t)e * 2 + which) * 512);
    float4 va = ar[t], vb = br[t];
    float4 v;
    v.x = va.x + vb.x; v.y = va.y + vb.y; v.z = va.z + vb.z; v.w = va.w + vb.w;
    float s = v.x + v.y + v.z + v.w;
    float q = v.x*v.x + v.y*v.y + v.z*v.z + v.w*v.w;
#pragma unroll
    for (int o = 16; o; o >>= 1) {
        s += __shfl_xor_sync(0xffffffffu, s, o);
        q += __shfl_xor_sync(0xffffffffu, q, o);
    }
    __shared__ float ss[4], sq[4];
    int w = t >> 5;
    if ((t & 31) == 0) { ss[w] = s; sq[w] = q; }
    __syncthreads();
    s = ss[0] + ss[1] + ss[2] + ss[3];
    q = sq[0] + sq[1] + sq[2] + sq[3];
    float mean = s * (1.f / 512.f);
    float var  = q * (1.f / 512.f) - mean * mean;
    float inv  = rsqrtf(var + 1e-5f);
    float4 g4 = gr[t], b4 = be[t];
    float4 o4;
    o4.x = (v.x - mean) * inv * g4.x + b4.x;
    o4.y = (v.y - mean) * inv * g4.y + b4.y;
    o4.z = (v.z - mean) * inv * g4.z + b4.z;
    o4.w = (v.w - mean) * inv * g4.w + b4.w;
    ((float4*)(y + (size_t)row * 512))[t] = o4;
}

// ---------------- row softmax (cols multiple of 256, <= 8192) ---------------
__global__ void softmax_kernel(float* __restrict__ data, int cols)
{
    int row = blockIdx.x, t = threadIdx.x;
    float* p = data + (size_t)row * cols;
    int cnt = cols >> 8;
    float v[32];
    float lmax = -INFINITY;
#pragma unroll
    for (int i = 0; i < 32; i++) {
        if (i < cnt) {
            v[i] = p[t + i * 256];
            lmax = fmaxf(lmax, v[i]);
        }
    }
    __shared__ float sh[8];
#pragma unroll
    for (int o = 16; o; o >>= 1) lmax = fmaxf(lmax, __shfl_xor_sync(0xffffffffu, lmax, o));
    if ((t & 31) == 0) sh[t >> 5] = lmax;
    __syncthreads();
    float rowmax = sh[0];
#pragma unroll
    for (int i = 1; i < 8; i++) rowmax = fmaxf(rowmax, sh[i]);
    __syncthreads();
    float lsum = 0.f;
#pragma unroll
    for (int i = 0; i < 32; i++) {
        if (i < cnt) {
            v[i] = expf(v[i] - rowmax);
            lsum += v[i];
        }
    }
#pragma unroll
    for (int o = 16; o; o >>= 1) lsum += __shfl_xor_sync(0xffffffffu, lsum, o);
    if ((t & 31) == 0) sh[t >> 5] = lsum;
    __syncthreads();
    float rowsum = sh[0];
#pragma unroll
    for (int i = 1; i < 8; i++) rowsum += sh[i];
    float rinv = 1.f / rowsum;
#pragma unroll
    for (int i = 0; i < 32; i++)
        if (i < cnt) p[t + i * 256] = v[i] * rinv;
}

// ---------------- small kernels ----------------
__global__ void zero_kernel(float* __restrict__ p, size_t n)
{
    size_t i = (size_t)blockIdx.x * blockDim.x + threadIdx.x;
    if (i < n) p[i] = 0.f;
}

__global__ void newmem_kernel(const float* __restrict__ mem, const float* __restrict__ upd,
                              float* __restrict__ out, size_t n)
{
    size_t i = (size_t)blockIdx.x * blockDim.x + threadIdx.x;
    if (i < n) {
        float u = fminf(fmaxf(0.1f * upd[i], -0.1f), 0.1f);
        out[i] = 0.9f * mem[i] + u;
    }
}

__global__ void pooled_kernel(const float* __restrict__ o, float* __restrict__ p)
{
    int e = blockIdx.y;
    int d = blockIdx.x * 256 + threadIdx.x;
    const float* base = o + (size_t)e * ND_ + d;
    float s = 0.f;
    for (int n = 0; n < N_; n++) s += base[(size_t)n * 512];
    p[e * 512 + d] = s * (1.f / 2048.f);
}

__global__ void gate_kernel(const float* __restrict__ pooled, const float* __restrict__ gw,
                            float* __restrict__ gate, float* __restrict__ out_gate)
{
    int t = threadIdx.x;
    int e = t >> 5, lane = t & 31;
    float s = 0.f;
    for (int i = lane; i < 512; i += 32) s += pooled[e * 512 + i] * gw[i];
#pragma unroll
    for (int o = 16; o; o >>= 1) s += __shfl_xor_sync(0xffffffffu, s, o);
    __shared__ float sh[4];
    if (lane == 0) sh[e] = s;
    __syncthreads();
    if (t == 0) {
        float g[4], mx = -INFINITY;
        for (int i = 0; i < 4; i++) {
            g[i] = fminf(fmaxf(sh[i], -10.f), 10.f);
            mx = fmaxf(mx, g[i]);
        }
        float sum = 0.f;
        for (int i = 0; i < 4; i++) { g[i] = expf(g[i] - mx); sum += g[i]; }
        for (int i = 0; i < 4; i++) sh[i] = g[i] / sum;
    }
    __syncthreads();
    if (t < 4) { gate[t] = sh[t]; out_gate[t] = sh[t]; }
}

__global__ void fuse_kernel(const float* __restrict__ o, const float* __restrict__ gate,
                            float* __restrict__ out)
{
    size_t i = (size_t)blockIdx.x * blockDim.x + threadIdx.x;
    if (i < (size_t)ND_) {
        out[i] = gate[0] * o[i] + gate[1] * o[ND_ + i]
               + gate[2] * o[2 * (size_t)ND_ + i] + gate[3] * o[3 * (size_t)ND_ + i];
    }
}

// ---------------- orchestration ----------------
static inline dim3 g2(int M, int N, int Z) { return dim3((N + 127) / 128, (M + 127) / 128, Z); }

extern "C" void kernel_launch(void* const* d_in, const int* in_sizes, int n_in,
                              void* d_out, int out_size)
{
    const float* tokens    = (const float*)d_in[0];
    const float* attn_wqkv = (const float*)d_in[1];
    const float* attn_bqkv = (const float*)d_in[2];
    const float* attn_wo   = (const float*)d_in[3];
    const float* attn_bo   = (const float*)d_in[4];
    const float* ln_g      = (const float*)d_in[5];
    const float* ln_b      = (const float*)d_in[6];
    const float* ffn_w1    = (const float*)d_in[7];
    const float* ffn_b1    = (const float*)d_in[8];
    const float* ffn_w2    = (const float*)d_in[9];
    const float* ffn_b2    = (const float*)d_in[10];
    const float* memories  = (const float*)d_in[11];
    const float* agg_w     = (const float*)d_in[12];
    const float* agg_b     = (const float*)d_in[13];
    const float* gate_w    = (const float*)d_in[14];

    float* out = (float*)d_out;
    float* out_fused = out;                       // [N, D]
    float* out_gate  = out + (size_t)ND_;         // [E]
    float* out_mem   = out + (size_t)ND_ + 4;     // [L, M, D]

    float *ln_tok, *cross, *big, *q, *k, *v, *ao, *eo, *retr, *outb, *upd, *pool, *gate;
    cudaGetSymbolAddress((void**)&ln_tok, g_ln_tok);
    cudaGetSymbolAddress((void**)&cross,  g_cross);
    cudaGetSymbolAddress((void**)&big,    g_big);
    cudaGetSymbolAddress((void**)&q,      g_q);
    cudaGetSymbolAddress((void**)&k,      g_k);
    cudaGetSymbolAddress((void**)&v,      g_v);
    cudaGetSymbolAddress((void**)&ao,     g_ao);
    cudaGetSymbolAddress((void**)&eo,     g_eo);
    cudaGetSymbolAddress((void**)&retr,   g_retr);
    cudaGetSymbolAddress((void**)&outb,   g_outb);
    cudaGetSymbolAddress((void**)&upd,    g_upd);
    cudaGetSymbolAddress((void**)&pool,   g_pool);
    cudaGetSymbolAddress((void**)&gate,   g_gate);
    float* h1 = big;   // alias: ffn hidden lives where attn scores were (dead by then)

    const float rsD = 1.0f / sqrtf(512.f);

    // 1. ln_tok = LN(tokens), no affine
    ln_kernel<<<EN_, 128>>>(tokens, ln_tok);

    // 2. cross logits = clip(ln_tok @ ln_tok^T / sqrt(D)), own-expert block -> -inf
    gemm_k<1, false, true, false><<<g2(EN_, EN_, 1), 256>>>(
        EN_, EN_, D_, rsD, ln_tok, D_, 0, ln_tok, D_, 0, big, EN_, 0,
        nullptr, 0, nullptr, 0, N_);

    // 3. softmax over 8192
    softmax_kernel<<<EN_, 256>>>(big, EN_);

    // 4. expert_in = ln_tok + P @ ln_tok
    gemm_k<5, false, false, false><<<g2(EN_, D_, 1), 256>>>(
        EN_, D_, EN_, 1.0f, big, EN_, 0, ln_tok, D_, 0, cross, D_, 0,
        nullptr, 0, ln_tok, 0, 0);

    // 5. q/k/v = x @ w^T + b  (batched over experts)
    {
        float* dst[3] = {q, k, v};
        for (int wsel = 0; wsel < 3; wsel++) {
            gemm_k<3, false, true, false><<<g2(N_, D_, E_), 256>>>(
                N_, D_, D_, 1.0f,
                cross, D_, ND_,
                attn_wqkv + (size_t)wsel * DD_, D_, (size_t)3 * DD_,
                dst[wsel], D_, ND_,
                attn_bqkv + (size_t)wsel * D_, (size_t)3 * D_,
                nullptr, 0, 0);
        }
    }

    // 6-8. attention core, per expert (scores reuse front of big)
    for (int e = 0; e < E_; e++) {
        gemm_k<0, false, true, false><<<g2(N_, N_, 8), 256>>>(
            N_, N_, 64, 0.125f,
            q + (size_t)e * ND_, D_, 64,
            k + (size_t)e * ND_, D_, 64,
            big, N_, (size_t)NM_,
            nullptr, 0, nullptr, 0, 0);
        softmax_kernel<<<8 * N_, 256>>>(big, N_);
        gemm_k<0, false, false, true><<<g2(N_, 64, 8), 256>>>(
            N_, 64, N_, 1.0f,
            big, N_, (size_t)NM_,
            v + (size_t)e * ND_, D_, 64,
            ao + (size_t)e * ND_, D_, 64,
            nullptr, 0, nullptr, 0, 0);
    }

    // 9. proj = o @ wo^T + bo (into q, reuse)
    gemm_k<3, false, true, false><<<g2(N_, D_, E_), 256>>>(
        N_, D_, D_, 1.0f, ao, D_, ND_, attn_wo, D_, DD_, q, D_, ND_,
        attn_bo, D_, nullptr, 0, 0);

    // 10. x1 = LN(expert_in + proj) (into ao, reuse)
    addln_kernel<<<EN_, 128>>>(cross, q, ln_g, ln_b, ao, 0);

    // 11. h = relu(x1 @ w1^T + b1)   (h1 aliases big; scores dead now)
    gemm_k<4, false, true, false><<<g2(N_, F_, E_), 256>>>(
        N_, F_, D_, 1.0f, ao, D_, ND_, ffn_w1, D_, (size_t)F_ * D_, h1, F_, (size_t)N_ * F_,
        ffn_b1, F_, nullptr, 0, 0);

    // 12. f2 = h @ w2^T + b2 (into q)
    gemm_k<3, false, true, false><<<g2(N_, D_, E_), 256>>>(
        N_, D_, F_, 1.0f, h1, F_, (size_t)N_ * F_, ffn_w2, F_, (size_t)D_ * F_, q, D_, ND_,
        ffn_b2, D_, nullptr, 0, 0);

    // 13. expert_out = LN(x1 + f2)
    addln_kernel<<<EN_, 128>>>(ao, q, ln_g, ln_b, eo, 1);

    // 14. mem logits per memory layer (batched over e), clip +-10
    for (int l = 0; l < L_; l++) {
        gemm_k<2, false, true, false><<<g2(N_, M_, E_), 256>>>(
            N_, M_, D_, rsD,
            eo, D_, ND_,
            memories + (size_t)l * M_ * D_, D_, 0,
            big + (size_t)l * NM_, M_, (size_t)L_ * NM_,
            nullptr, 0, nullptr, 0, 0);
    }
    // 15. softmax over M
    softmax_kernel<<<E_ * L_ * N_, 256>>>(big, M_);

    // 16. retrieval -> cat layout [e][n][l*512+d]
    for (int l = 0; l < L_; l++) {
        gemm_k<0, false, false, false><<<g2(N_, D_, E_), 256>>>(
            N_, D_, M_, 1.0f,
            big + (size_t)l * NM_, M_, (size_t)L_ * NM_,
            memories + (size_t)l * M_ * D_, D_, 0,
            retr + (size_t)l * D_, L_ * D_, (size_t)N_ * L_ * D_,
            nullptr, 0, nullptr, 0, 0);
    }

    // 17. upd = sum_e clip(attn^T @ expert_out, -1, 1)
    zero_kernel<<<(L_ * M_ * D_ + 255) / 256, 256>>>(upd, (size_t)L_ * M_ * D_);
    for (int e = 0; e < E_; e++) {
        gemm_k<6, true, false, false><<<g2(M_, D_, L_), 256>>>(
            M_, D_, N_, 1.0f,
            big + (size_t)e * L_ * NM_, M_, (size_t)NM_,
            eo + (size_t)e * ND_, D_, 0,
            upd, D_, (size_t)M_ * D_,
            nullptr, 0, nullptr, 0, 0);
    }

    // 18. new_mem
    newmem_kernel<<<(L_ * M_ * D_ + 255) / 256, 256>>>(memories, upd, out_mem, (size_t)L_ * M_ * D_);

    // 19. out = expert_out + cat @ agg_w^T + agg_b
    gemm_k<5, false, true, false><<<g2(N_, D_, E_), 256>>>(
        N_, D_, L_ * D_, 1.0f,
        retr, L_ * D_, (size_t)N_ * L_ * D_,
        agg_w, L_ * D_, 0,
        outb, D_, ND_,
        agg_b, 0, eo, ND_, 0);

    // 20-22. gating fusion
    pooled_kernel<<<dim3(2, E_), 256>>>(outb, pool);
    gate_kernel<<<1, 128>>>(pool, gate_w, gate, out_gate);
    fuse_kernel<<<(ND_ + 255) / 256, 256>>>(outb, gate, out_fused);

    (void)in_sizes; (void)n_in; (void)out_size;
}

// round 3
// speedup vs baseline: 1.7203x; 1.7203x over previous
#include <cuda_runtime.h>
#include <cuda_bf16.h>
#include <math.h>
#include <stdint.h>

// ---------------- problem constants ----------------
#define E_  4
#define N_  2048
#define D_  512
#define M_  2048
#define L_  3
#define F_  2048
#define EN_ (E_*N_)            // 8192
#define ND_ (N_*D_)            // 1048576
#define NM_ (N_*M_)            // 4194304
#define DD_ (D_*D_)            // 262144

// ---------------- scratch (static device arrays; no allocation) -------------
__device__ float g_ln_tok[EN_*D_];
__device__ float g_cross [EN_*D_];
__device__ float g_big   [EN_*EN_];
__device__ float g_q     [EN_*D_];
__device__ float g_k     [EN_*D_];
__device__ float g_v     [EN_*D_];
__device__ float g_ao    [EN_*D_];
__device__ float g_eo    [EN_*D_];
__device__ float g_retr  [E_*N_*L_*D_];
__device__ float g_outb  [EN_*D_];
__device__ float g_upd   [L_*M_*D_];
__device__ float g_pool  [E_*D_];
__device__ float g_gate  [E_];

// ============================================================================
// Tensor-core GEMM: fp32 via bf16 split (hi+lo, 3 MMA terms), fp32 accumulate.
// C[m,n] = epi( alpha * sum_k opA(A)[m,k]*opB(B)[k,n] )
// Block tile 128x128, k-step 16 (fp32), 8 warps of 32m x 64n, double-buffered.
// EPI: 0 none | 1 clip10+blockmask | 2 clip10 | 3 +bias | 4 relu(+bias)
//      5 +bias?+addend | 6 C += clip(v,-1,1)
// ============================================================================

#define TCSK 20   // smem row stride in bf16 elements (16 used + pad)

#define MMA_BF16(d, a, b0v, b1v) \
    asm volatile("mma.sync.aligned.m16n8k16.row.col.f32.bf16.bf16.f32 " \
                 "{%0,%1,%2,%3}, {%4,%5,%6,%7}, {%8,%9}, {%0,%1,%2,%3};\n" \
                 : "+f"(d[0]), "+f"(d[1]), "+f"(d[2]), "+f"(d[3]) \
                 : "r"(a[0]), "r"(a[1]), "r"(a[2]), "r"(a[3]), "r"(b0v), "r"(b1v))

__device__ __forceinline__ uint32_t lds32(const __nv_bfloat16* p) {
    return *reinterpret_cast<const uint32_t*>(p);
}

__device__ __forceinline__ void split_bf16(float v, __nv_bfloat16& hi, __nv_bfloat16& lo) {
    hi = __float2bfloat16_rn(v);
    lo = __float2bfloat16_rn(v - __bfloat162float(hi));
}

template<int EPI>
__device__ __forceinline__ void epi_store(float* __restrict__ C, int ldc,
                                          int gm, int gn, float v,
                                          const float* __restrict__ bias,
                                          const float* __restrict__ addend,
                                          int maskDiv)
{
    size_t ci = (size_t)gm * ldc + gn;
    if (EPI == 1) {
        v = fminf(fmaxf(v, -10.f), 10.f);
        if (gm / maskDiv == gn / maskDiv) v = -INFINITY;
        C[ci] = v;
    } else if (EPI == 2) {
        C[ci] = fminf(fmaxf(v, -10.f), 10.f);
    } else if (EPI == 3) {
        C[ci] = v + bias[gn];
    } else if (EPI == 4) {
        C[ci] = fmaxf(v + bias[gn], 0.f);
    } else if (EPI == 5) {
        if (bias) v += bias[gn];
        C[ci] = v + addend[ci];
    } else if (EPI == 6) {
        C[ci] += fminf(fmaxf(v, -1.f), 1.f);
    } else {
        C[ci] = v;
    }
}

template<int EPI, bool TA, bool TB, bool BOUND>
__global__ __launch_bounds__(256)
void tc_gemm(int M, int N, int K, float alpha,
             const float* __restrict__ A, int lda, size_t sA_,
             const float* __restrict__ B, int ldb, size_t sB_,
             float* __restrict__ C, int ldc, size_t sC_,
             const float* __restrict__ bias, size_t sBias,
             const float* __restrict__ addend, size_t sAdd,
             int maskDiv)
{
    const int z = blockIdx.z;
    A += (size_t)z * sA_;
    B += (size_t)z * sB_;
    C += (size_t)z * sC_;
    if (bias)   bias   += (size_t)z * sBias;
    if (addend) addend += (size_t)z * sAdd;

    const int m0 = blockIdx.y * 128;
    const int n0 = blockIdx.x * 128;

    // [stage][hi/lo][128 rows * TCSK]
    __shared__ __nv_bfloat16 shA[2][2][128 * TCSK];
    __shared__ __nv_bfloat16 shB[2][2][128 * TCSK];

    const int tid  = threadIdx.x;
    const int lane = tid & 31;
    const int wid  = tid >> 5;
    const int warp_m = (wid & 3) * 32;   // 4 warps along m
    const int warp_n = (wid >> 2) * 64;  // 2 warps along n
    const int g = lane >> 2;             // 0..7
    const int t = lane & 3;              // 0..3

    float acc[2][8][4];
#pragma unroll
    for (int i = 0; i < 2; i++)
#pragma unroll
        for (int j = 0; j < 8; j++)
#pragma unroll
            for (int c = 0; c < 4; c++) acc[i][j][c] = 0.f;

    const int KS = K >> 4;

    float pa[8], pb[8];

    // ---- loader lambdas (all 256 threads participate in each) ----
    auto g2r = [&](int ks) {
        const int kk = ks << 4;
        // ---- A ----
        if (!TA) {
            int row = tid >> 1, half = tid & 1;
            int gm = m0 + row;
            if (!BOUND || gm < M) {
                const float* p = A + (size_t)gm * lda + kk + half * 8;
                float4 x = *(const float4*)p;
                float4 y = *(const float4*)(p + 4);
                pa[0]=x.x; pa[1]=x.y; pa[2]=x.z; pa[3]=x.w;
                pa[4]=y.x; pa[5]=y.y; pa[6]=y.z; pa[7]=y.w;
            } else {
#pragma unroll
                for (int j = 0; j < 8; j++) pa[j] = 0.f;
            }
        } else {
            int kr = tid >> 4, mseg = (tid & 15) * 8;
            const float* p = A + (size_t)(kk + kr) * lda + m0 + mseg;
            if (!BOUND) {
                float4 x = *(const float4*)p;
                float4 y = *(const float4*)(p + 4);
                pa[0]=x.x; pa[1]=x.y; pa[2]=x.z; pa[3]=x.w;
                pa[4]=y.x; pa[5]=y.y; pa[6]=y.z; pa[7]=y.w;
            } else {
#pragma unroll
                for (int j = 0; j < 8; j++)
                    pa[j] = (m0 + mseg + j < M) ? p[j] : 0.f;
            }
        }
        // ---- B ----
        if (TB) {     // B[n][k]
            int row = tid >> 1, half = tid & 1;
            int gn = n0 + row;
            if (!BOUND || gn < N) {
                const float* p = B + (size_t)gn * ldb + kk + half * 8;
                float4 x = *(const float4*)p;
                float4 y = *(const float4*)(p + 4);
                pb[0]=x.x; pb[1]=x.y; pb[2]=x.z; pb[3]=x.w;
                pb[4]=y.x; pb[5]=y.y; pb[6]=y.z; pb[7]=y.w;
            } else {
#pragma unroll
                for (int j = 0; j < 8; j++) pb[j] = 0.f;
            }
        } else {      // B[k][n]
            int kr = tid >> 4, nseg = (tid & 15) * 8;
            const float* p = B + (size_t)(kk + kr) * ldb + n0 + nseg;
            if (!BOUND) {
                float4 x = *(const float4*)p;
                float4 y = *(const float4*)(p + 4);
                pb[0]=x.x; pb[1]=x.y; pb[2]=x.z; pb[3]=x.w;
                pb[4]=y.x; pb[5]=y.y; pb[6]=y.z; pb[7]=y.w;
            } else {
#pragma unroll
                for (int j = 0; j < 8; j++)
                    pb[j] = (n0 + nseg + j < N) ? p[j] : 0.f;
            }
        }
    };

    auto r2s = [&](int stage) {
        __nv_bfloat16* Ah = shA[stage][0];
        __nv_bfloat16* Al = shA[stage][1];
        __nv_bfloat16* Bh = shB[stage][0];
        __nv_bfloat16* Bl = shB[stage][1];
        if (!TA) {
            int row = tid >> 1, half = tid & 1;
            int base = row * TCSK + half * 8;
#pragma unroll
            for (int j = 0; j < 8; j++) {
                __nv_bfloat16 hi, lo; split_bf16(pa[j], hi, lo);
                Ah[base + j] = hi; Al[base + j] = lo;
            }
        } else {
            int kr = tid >> 4, mseg = (tid & 15) * 8;
#pragma unroll
            for (int j = 0; j < 8; j++) {
                __nv_bfloat16 hi, lo; split_bf16(pa[j], hi, lo);
                Ah[(mseg + j) * TCSK + kr] = hi;
                Al[(mseg + j) * TCSK + kr] = lo;
            }
        }
        if (TB) {
            int row = tid >> 1, half = tid & 1;
            int base = row * TCSK + half * 8;
#pragma unroll
            for (int j = 0; j < 8; j++) {
                __nv_bfloat16 hi, lo; split_bf16(pb[j], hi, lo);
                Bh[base + j] = hi; Bl[base + j] = lo;
            }
        } else {
            int kr = tid >> 4, nseg = (tid & 15) * 8;
#pragma unroll
            for (int j = 0; j < 8; j++) {
                __nv_bfloat16 hi, lo; split_bf16(pb[j], hi, lo);
                Bh[(nseg + j) * TCSK + kr] = hi;
                Bl[(nseg + j) * TCSK + kr] = lo;
            }
        }
    };

    // prologue: fill stage 0
    g2r(0);
    r2s(0);
    __syncthreads();

    for (int ks = 0; ks < KS; ks++) {
        const int cur = ks & 1;
        if (ks + 1 < KS) g2r(ks + 1);

        const __nv_bfloat16* Ah = shA[cur][0];
        const __nv_bfloat16* Al = shA[cur][1];
        const __nv_bfloat16* Bh = shB[cur][0];
        const __nv_bfloat16* Bl = shB[cur][1];

        uint32_t ah[2][4], al[2][4];
#pragma unroll
        for (int mt = 0; mt < 2; mt++) {
            int r = warp_m + mt * 16;
            ah[mt][0] = lds32(Ah + (r + g)     * TCSK + 2 * t);
            ah[mt][1] = lds32(Ah + (r + g + 8) * TCSK + 2 * t);
            ah[mt][2] = lds32(Ah + (r + g)     * TCSK + 8 + 2 * t);
            ah[mt][3] = lds32(Ah + (r + g + 8) * TCSK + 8 + 2 * t);
            al[mt][0] = lds32(Al + (r + g)     * TCSK + 2 * t);
            al[mt][1] = lds32(Al + (r + g + 8) * TCSK + 2 * t);
            al[mt][2] = lds32(Al + (r + g)     * TCSK + 8 + 2 * t);
            al[mt][3] = lds32(Al + (r + g + 8) * TCSK + 8 + 2 * t);
        }
#pragma unroll
        for (int nt = 0; nt < 8; nt++) {
            int c = warp_n + nt * 8;
            uint32_t bh0 = lds32(Bh + (c + g) * TCSK + 2 * t);
            uint32_t bh1 = lds32(Bh + (c + g) * TCSK + 8 + 2 * t);
            uint32_t bl0 = lds32(Bl + (c + g) * TCSK + 2 * t);
            uint32_t bl1 = lds32(Bl + (c + g) * TCSK + 8 + 2 * t);
#pragma unroll
            for (int mt = 0; mt < 2; mt++) {
                MMA_BF16(acc[mt][nt], ah[mt], bh0, bh1);
                MMA_BF16(acc[mt][nt], ah[mt], bl0, bl1);
                MMA_BF16(acc[mt][nt], al[mt], bh0, bh1);
            }
        }

        if (ks + 1 < KS) {
            r2s((ks + 1) & 1);
            __syncthreads();
        }
    }

    // ---- epilogue ----
#pragma unroll
    for (int mt = 0; mt < 2; mt++) {
        int gm0 = m0 + warp_m + mt * 16 + g;
        int gm1 = gm0 + 8;
#pragma unroll
        for (int nt = 0; nt < 8; nt++) {
            int gn = n0 + warp_n + nt * 8 + 2 * t;
            float c0 = alpha * acc[mt][nt][0];
            float c1 = alpha * acc[mt][nt][1];
            float c2 = alpha * acc[mt][nt][2];
            float c3 = alpha * acc[mt][nt][3];
            if (!BOUND || (gm0 < M && gn < N))
                epi_store<EPI>(C, ldc, gm0, gn,     c0, bias, addend, maskDiv);
            if (!BOUND || (gm0 < M && gn + 1 < N))
                epi_store<EPI>(C, ldc, gm0, gn + 1, c1, bias, addend, maskDiv);
            if (!BOUND || (gm1 < M && gn < N))
                epi_store<EPI>(C, ldc, gm1, gn,     c2, bias, addend, maskDiv);
            if (!BOUND || (gm1 < M && gn + 1 < N))
                epi_store<EPI>(C, ldc, gm1, gn + 1, c3, bias, addend, maskDiv);
        }
    }
}

// ---------------- layernorm (row length 512, 128 threads/block) -------------
__global__ void ln_kernel(const float* __restrict__ x, float* __restrict__ y)
{
    int row = blockIdx.x, t = threadIdx.x;
    const float4* xr = (const float4*)(x + (size_t)row * 512);
    float4 v = xr[t];
    float s = v.x + v.y + v.z + v.w;
    float q = v.x*v.x + v.y*v.y + v.z*v.z + v.w*v.w;
#pragma unroll
    for (int o = 16; o; o >>= 1) {
        s += __shfl_xor_sync(0xffffffffu, s, o);
        q += __shfl_xor_sync(0xffffffffu, q, o);
    }
    __shared__ float ss[4], sq[4];
    int w = t >> 5;
    if ((t & 31) == 0) { ss[w] = s; sq[w] = q; }
    __syncthreads();
    s = ss[0] + ss[1] + ss[2] + ss[3];
    q = sq[0] + sq[1] + sq[2] + sq[3];
    float mean = s * (1.f / 512.f);
    float var  = q * (1.f / 512.f) - mean * mean;
    float inv  = rsqrtf(var + 1e-5f);
    float4 o4;
    o4.x = (v.x - mean) * inv;
    o4.y = (v.y - mean) * inv;
    o4.z = (v.z - mean) * inv;
    o4.w = (v.w - mean) * inv;
    ((float4*)(y + (size_t)row * 512))[t] = o4;
}

__global__ void addln_kernel(const float* __restrict__ a, const float* __restrict__ b,
                             const float* __restrict__ gamma, const float* __restrict__ beta,
                             float* __restrict__ y, int which)
{
    int row = blockIdx.x, t = threadIdx.x;
    int e = row >> 11;
    const float4* ar = (const float4*)(a + (size_t)row * 512);
    const float4* br = (const float4*)(b + (size_t)row * 512);
    const float4* gr = (const float4*)(gamma + ((size_t)e * 2 + which) * 512);
    const float4* be = (const float4*)(beta  + ((size_t)e * 2 + which) * 512);
    float4 va = ar[t], vb = br[t];
    float4 v;
    v.x = va.x + vb.x; v.y = va.y + vb.y; v.z = va.z + vb.z; v.w = va.w + vb.w;
    float s = v.x + v.y + v.z + v.w;
    float q = v.x*v.x + v.y*v.y + v.z*v.z + v.w*v.w;
#pragma unroll
    for (int o = 16; o; o >>= 1) {
        s += __shfl_xor_sync(0xffffffffu, s, o);
        q += __shfl_xor_sync(0xffffffffu, q, o);
    }
    __shared__ float ss[4], sq[4];
    int w = t >> 5;
    if ((t & 31) == 0) { ss[w] = s; sq[w] = q; }
    __syncthreads();
    s = ss[0] + ss[1] + ss[2] + ss[3];
    q = sq[0] + sq[1] + sq[2] + sq[3];
    float mean = s * (1.f / 512.f);
    float var  = q * (1.f / 512.f) - mean * mean;
    float inv  = rsqrtf(var + 1e-5f);
    float4 g4 = gr[t], b4 = be[t];
    float4 o4;
    o4.x = (v.x - mean) * inv * g4.x + b4.x;
    o4.y = (v.y - mean) * inv * g4.y + b4.y;
    o4.z = (v.z - mean) * inv * g4.z + b4.z;
    o4.w = (v.w - mean) * inv * g4.w + b4.w;
    ((float4*)(y + (size_t)row * 512))[t] = o4;
}

// ---------------- row softmax (cols multiple of 256, <= 8192) ---------------
__global__ void softmax_kernel(float* __restrict__ data, int cols)
{
    int row = blockIdx.x, t = threadIdx.x;
    float* p = data + (size_t)row * cols;
    int cnt = cols >> 8;
    float v[32];
    float lmax = -INFINITY;
#pragma unroll
    for (int i = 0; i < 32; i++) {
        if (i < cnt) {
            v[i] = p[t + i * 256];
            lmax = fmaxf(lmax, v[i]);
        }
    }
    __shared__ float sh[8];
#pragma unroll
    for (int o = 16; o; o >>= 1) lmax = fmaxf(lmax, __shfl_xor_sync(0xffffffffu, lmax, o));
    if ((t & 31) == 0) sh[t >> 5] = lmax;
    __syncthreads();
    float rowmax = sh[0];
#pragma unroll
    for (int i = 1; i < 8; i++) rowmax = fmaxf(rowmax, sh[i]);
    __syncthreads();
    float lsum = 0.f;
#pragma unroll
    for (int i = 0; i < 32; i++) {
        if (i < cnt) {
            v[i] = expf(v[i] - rowmax);
            lsum += v[i];
        }
    }
#pragma unroll
    for (int o = 16; o; o >>= 1) lsum += __shfl_xor_sync(0xffffffffu, lsum, o);
    if ((t & 31) == 0) sh[t >> 5] = lsum;
    __syncthreads();
    float rowsum = sh[0];
#pragma unroll
    for (int i = 1; i < 8; i++) rowsum += sh[i];
    float rinv = 1.f / rowsum;
#pragma unroll
    for (int i = 0; i < 32; i++)
        if (i < cnt) p[t + i * 256] = v[i] * rinv;
}

// ---------------- small kernels ----------------
__global__ void zero_kernel(float* __restrict__ p, size_t n)
{
    size_t i = (size_t)blockIdx.x * blockDim.x + threadIdx.x;
    if (i < n) p[i] = 0.f;
}

__global__ void newmem_kernel(const float* __restrict__ mem, const float* __restrict__ upd,
                              float* __restrict__ out, size_t n)
{
    size_t i = (size_t)blockIdx.x * blockDim.x + threadIdx.x;
    if (i < n) {
        float u = fminf(fmaxf(0.1f * upd[i], -0.1f), 0.1f);
        out[i] = 0.9f * mem[i] + u;
    }
}

__global__ void pooled_kernel(const float* __restrict__ o, float* __restrict__ p)
{
    int e = blockIdx.y;
    int d = blockIdx.x * 256 + threadIdx.x;
    const float* base = o + (size_t)e * ND_ + d;
    float s = 0.f;
    for (int n = 0; n < N_; n++) s += base[(size_t)n * 512];
    p[e * 512 + d] = s * (1.f / 2048.f);
}

__global__ void gate_kernel(const float* __restrict__ pooled, const float* __restrict__ gw,
                            float* __restrict__ gate, float* __restrict__ out_gate)
{
    int t = threadIdx.x;
    int e = t >> 5, lane = t & 31;
    float s = 0.f;
    for (int i = lane; i < 512; i += 32) s += pooled[e * 512 + i] * gw[i];
#pragma unroll
    for (int o = 16; o; o >>= 1) s += __shfl_xor_sync(0xffffffffu, s, o);
    __shared__ float sh[4];
    if (lane == 0) sh[e] = s;
    __syncthreads();
    if (t == 0) {
        float g[4], mx = -INFINITY;
        for (int i = 0; i < 4; i++) {
            g[i] = fminf(fmaxf(sh[i], -10.f), 10.f);
            mx = fmaxf(mx, g[i]);
        }
        float sum = 0.f;
        for (int i = 0; i < 4; i++) { g[i] = expf(g[i] - mx); sum += g[i]; }
        for (int i = 0; i < 4; i++) sh[i] = g[i] / sum;
    }
    __syncthreads();
    if (t < 4) { gate[t] = sh[t]; out_gate[t] = sh[t]; }
}

__global__ void fuse_kernel(const float* __restrict__ o, const float* __restrict__ gate,
                            float* __restrict__ out)
{
    size_t i = (size_t)blockIdx.x * blockDim.x + threadIdx.x;
    if (i < (size_t)ND_) {
        out[i] = gate[0] * o[i] + gate[1] * o[ND_ + i]
               + gate[2] * o[2 * (size_t)ND_ + i] + gate[3] * o[3 * (size_t)ND_ + i];
    }
}

// ---------------- orchestration ----------------
static inline dim3 g2(int M, int N, int Z) { return dim3((N + 127) / 128, (M + 127) / 128, Z); }

extern "C" void kernel_launch(void* const* d_in, const int* in_sizes, int n_in,
                              void* d_out, int out_size)
{
    const float* tokens    = (const float*)d_in[0];
    const float* attn_wqkv = (const float*)d_in[1];
    const float* attn_bqkv = (const float*)d_in[2];
    const float* attn_wo   = (const float*)d_in[3];
    const float* attn_bo   = (const float*)d_in[4];
    const float* ln_g      = (const float*)d_in[5];
    const float* ln_b      = (const float*)d_in[6];
    const float* ffn_w1    = (const float*)d_in[7];
    const float* ffn_b1    = (const float*)d_in[8];
    const float* ffn_w2    = (const float*)d_in[9];
    const float* ffn_b2    = (const float*)d_in[10];
    const float* memories  = (const float*)d_in[11];
    const float* agg_w     = (const float*)d_in[12];
    const float* agg_b     = (const float*)d_in[13];
    const float* gate_w    = (const float*)d_in[14];

    float* out = (float*)d_out;
    float* out_fused = out;                       // [N, D]
    float* out_gate  = out + (size_t)ND_;         // [E]
    float* out_mem   = out + (size_t)ND_ + 4;     // [L, M, D]

    float *ln_tok, *cross, *big, *q, *k, *v, *ao, *eo, *retr, *outb, *upd, *pool, *gate;
    cudaGetSymbolAddress((void**)&ln_tok, g_ln_tok);
    cudaGetSymbolAddress((void**)&cross,  g_cross);
    cudaGetSymbolAddress((void**)&big,    g_big);
    cudaGetSymbolAddress((void**)&q,      g_q);
    cudaGetSymbolAddress((void**)&k,      g_k);
    cudaGetSymbolAddress((void**)&v,      g_v);
    cudaGetSymbolAddress((void**)&ao,     g_ao);
    cudaGetSymbolAddress((void**)&eo,     g_eo);
    cudaGetSymbolAddress((void**)&retr,   g_retr);
    cudaGetSymbolAddress((void**)&outb,   g_outb);
    cudaGetSymbolAddress((void**)&upd,    g_upd);
    cudaGetSymbolAddress((void**)&pool,   g_pool);
    cudaGetSymbolAddress((void**)&gate,   g_gate);
    float* h1 = big;   // alias: ffn hidden lives where attn scores were (dead by then)

    const float rsD = 1.0f / sqrtf(512.f);

    // 1. ln_tok = LN(tokens), no affine
    ln_kernel<<<EN_, 128>>>(tokens, ln_tok);

    // 2. cross logits = clip(ln_tok @ ln_tok^T / sqrt(D)), own-expert block -> -inf
    tc_gemm<1, false, true, false><<<g2(EN_, EN_, 1), 256>>>(
        EN_, EN_, D_, rsD, ln_tok, D_, 0, ln_tok, D_, 0, big, EN_, 0,
        nullptr, 0, nullptr, 0, N_);

    // 3. softmax over 8192
    softmax_kernel<<<EN_, 256>>>(big, EN_);

    // 4. expert_in = ln_tok + P @ ln_tok
    tc_gemm<5, false, false, false><<<g2(EN_, D_, 1), 256>>>(
        EN_, D_, EN_, 1.0f, big, EN_, 0, ln_tok, D_, 0, cross, D_, 0,
        nullptr, 0, ln_tok, 0, 0);

    // 5. q/k/v = x @ w^T + b  (batched over experts)
    {
        float* dst[3] = {q, k, v};
        for (int wsel = 0; wsel < 3; wsel++) {
            tc_gemm<3, false, true, false><<<g2(N_, D_, E_), 256>>>(
                N_, D_, D_, 1.0f,
                cross, D_, ND_,
                attn_wqkv + (size_t)wsel * DD_, D_, (size_t)3 * DD_,
                dst[wsel], D_, ND_,
                attn_bqkv + (size_t)wsel * D_, (size_t)3 * D_,
                nullptr, 0, 0);
        }
    }

    // 6-8. attention core, per expert (scores reuse front of big)
    for (int e = 0; e < E_; e++) {
        tc_gemm<0, false, true, false><<<g2(N_, N_, 8), 256>>>(
            N_, N_, 64, 0.125f,
            q + (size_t)e * ND_, D_, 64,
            k + (size_t)e * ND_, D_, 64,
            big, N_, (size_t)NM_,
            nullptr, 0, nullptr, 0, 0);
        softmax_kernel<<<8 * N_, 256>>>(big, N_);
        tc_gemm<0, false, false, true><<<g2(N_, 64, 8), 256>>>(
            N_, 64, N_, 1.0f,
            big, N_, (size_t)NM_,
            v + (size_t)e * ND_, D_, 64,
            ao + (size_t)e * ND_, D_, 64,
            nullptr, 0, nullptr, 0, 0);
    }

    // 9. proj = o @ wo^T + bo (into q, reuse)
    tc_gemm<3, false, true, false><<<g2(N_, D_, E_), 256>>>(
        N_, D_, D_, 1.0f, ao, D_, ND_, attn_wo, D_, DD_, q, D_, ND_,
        attn_bo, D_, nullptr, 0, 0);

    // 10. x1 = LN(expert_in + proj) (into ao, reuse)
    addln_kernel<<<EN_, 128>>>(cross, q, ln_g, ln_b, ao, 0);

    // 11. h = relu(x1 @ w1^T + b1)   (h1 aliases big; scores dead now)
    tc_gemm<4, false, true, false><<<g2(N_, F_, E_), 256>>>(
        N_, F_, D_, 1.0f, ao, D_, ND_, ffn_w1, D_, (size_t)F_ * D_, h1, F_, (size_t)N_ * F_,
        ffn_b1, F_, nullptr, 0, 0);

    // 12. f2 = h @ w2^T + b2 (into q)
    tc_gemm<3, false, true, false><<<g2(N_, D_, E_), 256>>>(
        N_, D_, F_, 1.0f, h1, F_, (size_t)N_ * F_, ffn_w2, F_, (size_t)D_ * F_, q, D_, ND_,
        ffn_b2, D_, nullptr, 0, 0);

    // 13. expert_out = LN(x1 + f2)
    addln_kernel<<<EN_, 128>>>(ao, q, ln_g, ln_b, eo, 1);

    // 14. mem logits per memory layer (batched over e), clip +-10
    for (int l = 0; l < L_; l++) {
        tc_gemm<2, false, true, false><<<g2(N_, M_, E_), 256>>>(
            N_, M_, D_, rsD,
            eo, D_, ND_,
            memories + (size_t)l * M_ * D_, D_, 0,
            big + (size_t)l * NM_, M_, (size_t)L_ * NM_,
            nullptr, 0, nullptr, 0, 0);
    }
    // 15. softmax over M
    softmax_kernel<<<E_ * L_ * N_, 256>>>(big, M_);

    // 16. retrieval -> cat layout [e][n][l*512+d]
    for (int l = 0; l < L_; l++) {
        tc_gemm<0, false, false, false><<<g2(N_, D_, E_), 256>>>(
            N_, D_, M_, 1.0f,
            big + (size_t)l * NM_, M_, (size_t)L_ * NM_,
            memories + (size_t)l * M_ * D_, D_, 0,
            retr + (size_t)l * D_, L_ * D_, (size_t)N_ * L_ * D_,
            nullptr, 0, nullptr, 0, 0);
    }

    // 17. upd = sum_e clip(attn^T @ expert_out, -1, 1)
    zero_kernel<<<(L_ * M_ * D_ + 255) / 256, 256>>>(upd, (size_t)L_ * M_ * D_);
    for (int e = 0; e < E_; e++) {
        tc_gemm<6, true, false, false><<<g2(M_, D_, L_), 256>>>(
            M_, D_, N_, 1.0f,
            big + (size_t)e * L_ * NM_, M_, (size_t)NM_,
            eo + (size_t)e * ND_, D_, 0,
            upd, D_, (size_t)M_ * D_,
            nullptr, 0, nullptr, 0, 0);
    }

    // 18. new_mem
    newmem_kernel<<<(L_ * M_ * D_ + 255) / 256, 256>>>(memories, upd, out_mem, (size_t)L_ * M_ * D_);

    // 19. out = expert_out + cat @ agg_w^T + agg_b
    tc_gemm<5, false, true, false><<<g2(N_, D_, E_), 256>>>(
        N_, D_, L_ * D_, 1.0f,
        retr, L_ * D_, (size_t)N_ * L_ * D_,
        agg_w, L_ * D_, 0,
        outb, D_, ND_,
        agg_b, 0, eo, ND_, 0);

    // 20-22. gating fusion
    pooled_kernel<<<dim3(2, E_), 256>>>(outb, pool);
    gate_kernel<<<1, 128>>>(pool, gate_w, gate, out_gate);
    fuse_kernel<<<(ND_ + 255) / 256, 256>>>(outb, gate, out_fused);

    (void)in_sizes; (void)n_in; (void)out_size;
}

// round 5
// speedup vs baseline: 2.7834x; 1.6179x over previous
#include <cuda_runtime.h>
#include <cuda_bf16.h>
#include <math.h>
#include <stdint.h>

// ---------------- problem constants ----------------
#define E_  4
#define N_  2048
#define D_  512
#define M_  2048
#define L_  3
#define F_  2048
#define EN_ (E_*N_)
#define ND_ (N_*D_)
#define NM_ (N_*M_)
#define DD_ (D_*D_)

// ---------------- scratch ----------------
__device__ float g_ln_tok[EN_*D_];
__device__ float g_cross [EN_*D_];
__device__ float g_big   [EN_*EN_];
__device__ float g_q     [EN_*D_];
__device__ float g_k     [EN_*D_];
__device__ float g_v     [EN_*D_];
__device__ float g_ao    [EN_*D_];
__device__ float g_eo    [EN_*D_];
__device__ float g_retr  [E_*N_*L_*D_];
__device__ float g_outb  [EN_*D_];
__device__ float g_upd   [L_*M_*D_];
__device__ float g_pool  [E_*D_];
__device__ float g_gate  [E_];

// ============================================================================
// Split-bf16 tensor-core GEMM, ldmatrix + vectorized STS.
// smem tile layouts: row-major24 (128 rows x 16 k, stride 24) for [m][k]/[n][k];
// trans136 (16 k-rows x 128 cols, stride 136) for [k][m]/[k][n].
// Planes per stage: Ah, Al, Bh, Bl each 3072 bf16 (6144B). 2 stages = 48KB.
// ============================================================================
#define MMA_BF16(d, a, b0v, b1v) \
    asm volatile("mma.sync.aligned.m16n8k16.row.col.f32.bf16.bf16.f32 " \
                 "{%0,%1,%2,%3}, {%4,%5,%6,%7}, {%8,%9}, {%0,%1,%2,%3};\n" \
                 : "+f"(d[0]), "+f"(d[1]), "+f"(d[2]), "+f"(d[3]) \
                 : "r"(a[0]), "r"(a[1]), "r"(a[2]), "r"(a[3]), "r"(b0v), "r"(b1v))

__device__ __forceinline__ void ldm4(uint32_t* r, uint32_t a){
  asm volatile("ldmatrix.sync.aligned.m8n8.x4.shared.b16 {%0,%1,%2,%3},[%4];"
    :"=r"(r[0]),"=r"(r[1]),"=r"(r[2]),"=r"(r[3]):"r"(a));
}
__device__ __forceinline__ void ldm4t(uint32_t* r, uint32_t a){
  asm volatile("ldmatrix.sync.aligned.m8n8.x4.trans.shared.b16 {%0,%1,%2,%3},[%4];"
    :"=r"(r[0]),"=r"(r[1]),"=r"(r[2]),"=r"(r[3]):"r"(a));
}

// split 8 floats into hi/lo packed words (4x uint32 each)
__device__ __forceinline__ void pack8(const float* v, uint32_t* hw, uint32_t* lw){
#pragma unroll
  for(int i=0;i<4;i++){
    __nv_bfloat162 h, l;
    h.x=__float2bfloat16_rn(v[2*i]);   l.x=__float2bfloat16_rn(v[2*i]  -__bfloat162float(h.x));
    h.y=__float2bfloat16_rn(v[2*i+1]); l.y=__float2bfloat16_rn(v[2*i+1]-__bfloat162float(h.y));
    hw[i]=*reinterpret_cast<uint32_t*>(&h);
    lw[i]=*reinterpret_cast<uint32_t*>(&l);
  }
}

template<int EPI>
__device__ __forceinline__ void epi_store(float* __restrict__ C, int ldc,
                                          int gm, int gn, float v,
                                          const float* __restrict__ bias,
                                          const float* __restrict__ addend,
                                          int maskDiv)
{
    size_t ci = (size_t)gm * ldc + gn;
    if (EPI == 1) {
        v = fminf(fmaxf(v, -10.f), 10.f);
        if (gm / maskDiv == gn / maskDiv) v = -INFINITY;
        C[ci] = v;
    } else if (EPI == 2) {
        C[ci] = fminf(fmaxf(v, -10.f), 10.f);
    } else if (EPI == 3) {
        C[ci] = v + bias[gn];
    } else if (EPI == 4) {
        C[ci] = fmaxf(v + bias[gn], 0.f);
    } else if (EPI == 5) {
        if (bias) v += bias[gn];
        C[ci] = v + addend[ci];
    } else if (EPI == 6) {
        C[ci] += fminf(fmaxf(v, -1.f), 1.f);
    } else {
        C[ci] = v;
    }
}

template<int EPI, bool TA, bool TB, bool BOUND>
__global__ __launch_bounds__(256)
void tc_gemm(int M, int N, int K, float alpha,
             const float* __restrict__ A, int lda, size_t sA_,
             const float* __restrict__ B, int ldb, size_t sB_,
             float* __restrict__ C, int ldc, size_t sC_,
             const float* __restrict__ bias, size_t sBias,
             const float* __restrict__ addend, size_t sAdd,
             int maskDiv)
{
    const int z = blockIdx.z;
    A += (size_t)z * sA_;
    B += (size_t)z * sB_;
    C += (size_t)z * sC_;
    if (bias)   bias   += (size_t)z * sBias;
    if (addend) addend += (size_t)z * sAdd;

    const int m0 = blockIdx.y * 128;
    const int n0 = blockIdx.x * 128;

    // [stage][plane: Ah,Al,Bh,Bl][3072]
    __shared__ __align__(16) __nv_bfloat16 sh[2][4][3072];
    const uint32_t sb = (uint32_t)__cvta_generic_to_shared(&sh[0][0][0]);

    const int tid  = threadIdx.x;
    const int lane = tid & 31;
    const int wid  = tid >> 5;
    const int warp_m = (wid & 3) * 32;
    const int warp_n = (wid >> 2) * 64;

    float acc[2][8][4];
#pragma unroll
    for (int i = 0; i < 2; i++)
#pragma unroll
        for (int j = 0; j < 8; j++)
#pragma unroll
            for (int c = 0; c < 4; c++) acc[i][j][c] = 0.f;

    const int KS = K >> 4;
    float pa[8], pb[8];

    auto g2r = [&](int ks) {
        const int kk = ks << 4;
        if (!TA) {
            int row = tid >> 1, half = tid & 1;
            int gm = m0 + row;
            const float* p = A + (size_t)gm * lda + kk + half * 8;
            if (!BOUND || gm < M) {
                float4 x = *(const float4*)p, y = *(const float4*)(p + 4);
                pa[0]=x.x; pa[1]=x.y; pa[2]=x.z; pa[3]=x.w;
                pa[4]=y.x; pa[5]=y.y; pa[6]=y.z; pa[7]=y.w;
            } else {
#pragma unroll
                for (int j = 0; j < 8; j++) pa[j] = 0.f;
            }
        } else {
            int kr = tid >> 4, seg = (tid & 15) * 8;
            const float* p = A + (size_t)(kk + kr) * lda + m0 + seg;
            if (!BOUND) {
                float4 x = *(const float4*)p, y = *(const float4*)(p + 4);
                pa[0]=x.x; pa[1]=x.y; pa[2]=x.z; pa[3]=x.w;
                pa[4]=y.x; pa[5]=y.y; pa[6]=y.z; pa[7]=y.w;
            } else {
#pragma unroll
                for (int j = 0; j < 8; j++) pa[j] = (m0 + seg + j < M) ? p[j] : 0.f;
            }
        }
        if (TB) {
            int row = tid >> 1, half = tid & 1;
            int gn = n0 + row;
            const float* p = B + (size_t)gn * ldb + kk + half * 8;
            if (!BOUND || gn < N) {
                float4 x = *(const float4*)p, y = *(const float4*)(p + 4);
                pb[0]=x.x; pb[1]=x.y; pb[2]=x.z; pb[3]=x.w;
                pb[4]=y.x; pb[5]=y.y; pb[6]=y.z; pb[7]=y.w;
            } else {
#pragma unroll
                for (int j = 0; j < 8; j++) pb[j] = 0.f;
            }
        } else {
            int kr = tid >> 4, seg = (tid & 15) * 8;
            const float* p = B + (size_t)(kk + kr) * ldb + n0 + seg;
            if (!BOUND) {
                float4 x = *(const float4*)p, y = *(const float4*)(p + 4);
                pb[0]=x.x; pb[1]=x.y; pb[2]=x.z; pb[3]=x.w;
                pb[4]=y.x; pb[5]=y.y; pb[6]=y.z; pb[7]=y.w;
            } else {
#pragma unroll
                for (int j = 0; j < 8; j++) pb[j] = (n0 + seg + j < N) ? p[j] : 0.f;
            }
        }
    };

    auto r2s = [&](int st) {
        uint32_t hw[4], lw[4];
        pack8(pa, hw, lw);
        {
            size_t off;
            if (!TA) { int row = tid >> 1, half = tid & 1; off = (size_t)row * 24 + half * 8; }
            else     { int kr = tid >> 4, seg = (tid & 15) * 8; off = (size_t)kr * 136 + seg; }
            *reinterpret_cast<uint4*>(&sh[st][0][off]) = make_uint4(hw[0],hw[1],hw[2],hw[3]);
            *reinterpret_cast<uint4*>(&sh[st][1][off]) = make_uint4(lw[0],lw[1],lw[2],lw[3]);
        }
        pack8(pb, hw, lw);
        {
            size_t off;
            if (TB)  { int row = tid >> 1, half = tid & 1; off = (size_t)row * 24 + half * 8; }
            else     { int kr = tid >> 4, seg = (tid & 15) * 8; off = (size_t)kr * 136 + seg; }
            *reinterpret_cast<uint4*>(&sh[st][2][off]) = make_uint4(hw[0],hw[1],hw[2],hw[3]);
            *reinterpret_cast<uint4*>(&sh[st][3][off]) = make_uint4(lw[0],lw[1],lw[2],lw[3]);
        }
    };

    g2r(0);
    r2s(0);
    __syncthreads();

    for (int ks = 0; ks < KS; ks++) {
        const int cur = ks & 1;
        if (ks + 1 < KS) g2r(ks + 1);

        const uint32_t pAh = sb + (uint32_t)(cur * 4 + 0) * 6144u;
        const uint32_t pAl = sb + (uint32_t)(cur * 4 + 1) * 6144u;
        const uint32_t pBh = sb + (uint32_t)(cur * 4 + 2) * 6144u;
        const uint32_t pBl = sb + (uint32_t)(cur * 4 + 3) * 6144u;

        // ldmatrix lane-address offsets (elements), then x2 bytes
        uint32_t ah[2][4], al[2][4];
#pragma unroll
        for (int mt = 0; mt < 2; mt++) {
            int r = warp_m + mt * 16;
            uint32_t off;
            if (!TA)
                off = (uint32_t)((r + (lane & 7) + ((lane >> 3) & 1) * 8) * 24
                                 + (lane >> 4) * 8) * 2u;
            else
                off = (uint32_t)(((((lane >> 4) & 1) * 8 + (lane & 7)) * 136)
                                 + r + ((lane >> 3) & 1) * 8) * 2u;
            if (!TA) { ldm4 (ah[mt], pAh + off); ldm4 (al[mt], pAl + off); }
            else     { ldm4t(ah[mt], pAh + off); ldm4t(al[mt], pAl + off); }
        }
        uint32_t bh[4][4], bl[4][4];
#pragma unroll
        for (int np = 0; np < 4; np++) {
            int c = warp_n + np * 16;
            uint32_t off;
            if (TB)
                off = (uint32_t)((c + (lane & 7) + ((lane >> 3) & 1) * 8) * 24
                                 + (lane >> 4) * 8) * 2u;
            else
                off = (uint32_t)(((((lane >> 4) & 1) * 8 + (lane & 7)) * 136)
                                 + c + ((lane >> 3) & 1) * 8) * 2u;
            if (TB) { ldm4 (bh[np], pBh + off); ldm4 (bl[np], pBl + off); }
            else    { ldm4t(bh[np], pBh + off); ldm4t(bl[np], pBl + off); }
        }

#pragma unroll
        for (int mt = 0; mt < 2; mt++)
#pragma unroll
            for (int np = 0; np < 4; np++) {
                MMA_BF16(acc[mt][np*2+0], ah[mt], bh[np][0], bh[np][2]);
                MMA_BF16(acc[mt][np*2+0], ah[mt], bl[np][0], bl[np][2]);
                MMA_BF16(acc[mt][np*2+0], al[mt], bh[np][0], bh[np][2]);
                MMA_BF16(acc[mt][np*2+1], ah[mt], bh[np][1], bh[np][3]);
                MMA_BF16(acc[mt][np*2+1], ah[mt], bl[np][1], bl[np][3]);
                MMA_BF16(acc[mt][np*2+1], al[mt], bh[np][1], bh[np][3]);
            }

        if (ks + 1 < KS) {
            r2s((ks + 1) & 1);
            __syncthreads();
        }
    }

    const int g = lane >> 2, t = lane & 3;
#pragma unroll
    for (int mt = 0; mt < 2; mt++) {
        int gm0 = m0 + warp_m + mt * 16 + g;
        int gm1 = gm0 + 8;
#pragma unroll
        for (int nt = 0; nt < 8; nt++) {
            int gn = n0 + warp_n + nt * 8 + 2 * t;
            float c0 = alpha * acc[mt][nt][0];
            float c1 = alpha * acc[mt][nt][1];
            float c2 = alpha * acc[mt][nt][2];
            float c3 = alpha * acc[mt][nt][3];
            if (!BOUND || (gm0 < M && gn < N))
                epi_store<EPI>(C, ldc, gm0, gn,     c0, bias, addend, maskDiv);
            if (!BOUND || (gm0 < M && gn + 1 < N))
                epi_store<EPI>(C, ldc, gm0, gn + 1, c1, bias, addend, maskDiv);
            if (!BOUND || (gm1 < M && gn < N))
                epi_store<EPI>(C, ldc, gm1, gn,     c2, bias, addend, maskDiv);
            if (!BOUND || (gm1 < M && gn + 1 < N))
                epi_store<EPI>(C, ldc, gm1, gn + 1, c3, bias, addend, maskDiv);
        }
    }
}

// ---------------- layernorm ----------------
__global__ void ln_kernel(const float* __restrict__ x, float* __restrict__ y)
{
    int row = blockIdx.x, t = threadIdx.x;
    const float4* xr = (const float4*)(x + (size_t)row * 512);
    float4 v = xr[t];
    float s = v.x + v.y + v.z + v.w;
    float q = v.x*v.x + v.y*v.y + v.z*v.z + v.w*v.w;
#pragma unroll
    for (int o = 16; o; o >>= 1) {
        s += __shfl_xor_sync(0xffffffffu, s, o);
        q += __shfl_xor_sync(0xffffffffu, q, o);
    }
    __shared__ float ss[4], sq[4];
    int w = t >> 5;
    if ((t & 31) == 0) { ss[w] = s; sq[w] = q; }
    __syncthreads();
    s = ss[0] + ss[1] + ss[2] + ss[3];
    q = sq[0] + sq[1] + sq[2] + sq[3];
    float mean = s * (1.f / 512.f);
    float var  = q * (1.f / 512.f) - mean * mean;
    float inv  = rsqrtf(var + 1e-5f);
    float4 o4;
    o4.x = (v.x - mean) * inv;
    o4.y = (v.y - mean) * inv;
    o4.z = (v.z - mean) * inv;
    o4.w = (v.w - mean) * inv;
    ((float4*)(y + (size_t)row * 512))[t] = o4;
}

__global__ void addln_kernel(const float* __restrict__ a, const float* __restrict__ b,
                             const float* __restrict__ gamma, const float* __restrict__ beta,
                             float* __restrict__ y, int which)
{
    int row = blockIdx.x, t = threadIdx.x;
    int e = row >> 11;
    const float4* ar = (const float4*)(a + (size_t)row * 512);
    const float4* br = (const float4*)(b + (size_t)row * 512);
    const float4* gr = (const float4*)(gamma + ((size_t)e * 2 + which) * 512);
    const float4* be = (const float4*)(beta  + ((size_t)e * 2 + which) * 512);
    float4 va = ar[t], vb = br[t];
    float4 v;
    v.x = va.x + vb.x; v.y = va.y + vb.y; v.z = va.z + vb.z; v.w = va.w + vb.w;
    float s = v.x + v.y + v.z + v.w;
    float q = v.x*v.x + v.y*v.y + v.z*v.z + v.w*v.w;
#pragma unroll
    for (int o = 16; o; o >>= 1) {
        s += __shfl_xor_sync(0xffffffffu, s, o);
        q += __shfl_xor_sync(0xffffffffu, q, o);
    }
    __shared__ float ss[4], sq[4];
    int w = t >> 5;
    if ((t & 31) == 0) { ss[w] = s; sq[w] = q; }
    __syncthreads();
    s = ss[0] + ss[1] + ss[2] + ss[3];
    q = sq[0] + sq[1] + sq[2] + sq[3];
    float mean = s * (1.f / 512.f);
    float var  = q * (1.f / 512.f) - mean * mean;
    float inv  = rsqrtf(var + 1e-5f);
    float4 g4 = gr[t], b4 = be[t];
    float4 o4;
    o4.x = (v.x - mean) * inv * g4.x + b4.x;
    o4.y = (v.y - mean) * inv * g4.y + b4.y;
    o4.z = (v.z - mean) * inv * g4.z + b4.z;
    o4.w = (v.w - mean) * inv * g4.w + b4.w;
    ((float4*)(y + (size_t)row * 512))[t] = o4;
}

// ---------------- row softmax ----------------
__global__ void softmax_kernel(float* __restrict__ data, int cols)
{
    int row = blockIdx.x, t = threadIdx.x;
    float* p = data + (size_t)row * cols;
    int cnt = cols >> 8;
    float v[32];
    float lmax = -INFINITY;
#pragma unroll
    for (int i = 0; i < 32; i++) {
        if (i < cnt) {
            v[i] = p[t + i * 256];
            lmax = fmaxf(lmax, v[i]);
        }
    }
    __shared__ float sh[8];
#pragma unroll
    for (int o = 16; o; o >>= 1) lmax = fmaxf(lmax, __shfl_xor_sync(0xffffffffu, lmax, o));
    if ((t & 31) == 0) sh[t >> 5] = lmax;
    __syncthreads();
    float rowmax = sh[0];
#pragma unroll
    for (int i = 1; i < 8; i++) rowmax = fmaxf(rowmax, sh[i]);
    __syncthreads();
    float lsum = 0.f;
#pragma unroll
    for (int i = 0; i < 32; i++) {
        if (i < cnt) {
            v[i] = expf(v[i] - rowmax);
            lsum += v[i];
        }
    }
#pragma unroll
    for (int o = 16; o; o >>= 1) lsum += __shfl_xor_sync(0xffffffffu, lsum, o);
    if ((t & 31) == 0) sh[t >> 5] = lsum;
    __syncthreads();
    float rowsum = sh[0];
#pragma unroll
    for (int i = 1; i < 8; i++) rowsum += sh[i];
    float rinv = 1.f / rowsum;
#pragma unroll
    for (int i = 0; i < 32; i++)
        if (i < cnt) p[t + i * 256] = v[i] * rinv;
}

// ---------------- small kernels ----------------
__global__ void zero_kernel(float* __restrict__ p, size_t n)
{
    size_t i = (size_t)blockIdx.x * blockDim.x + threadIdx.x;
    if (i < n) p[i] = 0.f;
}

__global__ void newmem_kernel(const float* __restrict__ mem, const float* __restrict__ upd,
                              float* __restrict__ out, size_t n)
{
    size_t i = (size_t)blockIdx.x * blockDim.x + threadIdx.x;
    if (i < n) {
        float u = fminf(fmaxf(0.1f * upd[i], -0.1f), 0.1f);
        out[i] = 0.9f * mem[i] + u;
    }
}

__global__ void pooled_kernel(const float* __restrict__ o, float* __restrict__ p)
{
    int e = blockIdx.y;
    int d = blockIdx.x * 256 + threadIdx.x;
    const float* base = o + (size_t)e * ND_ + d;
    float s = 0.f;
    for (int n = 0; n < N_; n++) s += base[(size_t)n * 512];
    p[e * 512 + d] = s * (1.f / 2048.f);
}

__global__ void gate_kernel(const float* __restrict__ pooled, const float* __restrict__ gw,
                            float* __restrict__ gate, float* __restrict__ out_gate)
{
    int t = threadIdx.x;
    int e = t >> 5, lane = t & 31;
    float s = 0.f;
    for (int i = lane; i < 512; i += 32) s += pooled[e * 512 + i] * gw[i];
#pragma unroll
    for (int o = 16; o; o >>= 1) s += __shfl_xor_sync(0xffffffffu, s, o);
    __shared__ float sh[4];
    if (lane == 0) sh[e] = s;
    __syncthreads();
    if (t == 0) {
        float g[4], mx = -INFINITY;
        for (int i = 0; i < 4; i++) {
            g[i] = fminf(fmaxf(sh[i], -10.f), 10.f);
            mx = fmaxf(mx, g[i]);
        }
        float sum = 0.f;
        for (int i = 0; i < 4; i++) { g[i] = expf(g[i] - mx); sum += g[i]; }
        for (int i = 0; i < 4; i++) sh[i] = g[i] / sum;
    }
    __syncthreads();
    if (t < 4) { gate[t] = sh[t]; out_gate[t] = sh[t]; }
}

__global__ void fuse_kernel(const float* __restrict__ o, const float* __restrict__ gate,
                            float* __restrict__ out)
{
    size_t i = (size_t)blockIdx.x * blockDim.x + threadIdx.x;
    if (i < (size_t)ND_) {
        out[i] = gate[0] * o[i] + gate[1] * o[ND_ + i]
               + gate[2] * o[2 * (size_t)ND_ + i] + gate[3] * o[3 * (size_t)ND_ + i];
    }
}

// ---------------- orchestration ----------------
static inline dim3 g2(int M, int N, int Z) { return dim3((N + 127) / 128, (M + 127) / 128, Z); }

extern "C" void kernel_launch(void* const* d_in, const int* in_sizes, int n_in,
                              void* d_out, int out_size)
{
    const float* tokens    = (const float*)d_in[0];
    const float* attn_wqkv = (const float*)d_in[1];
    const float* attn_bqkv = (const float*)d_in[2];
    const float* attn_wo   = (const float*)d_in[3];
    const float* attn_bo   = (const float*)d_in[4];
    const float* ln_g      = (const float*)d_in[5];
    const float* ln_b      = (const float*)d_in[6];
    const float* ffn_w1    = (const float*)d_in[7];
    const float* ffn_b1    = (const float*)d_in[8];
    const float* ffn_w2    = (const float*)d_in[9];
    const float* ffn_b2    = (const float*)d_in[10];
    const float* memories  = (const float*)d_in[11];
    const float* agg_w     = (const float*)d_in[12];
    const float* agg_b     = (const float*)d_in[13];
    const float* gate_w    = (const float*)d_in[14];

    float* out = (float*)d_out;
    float* out_fused = out;
    float* out_gate  = out + (size_t)ND_;
    float* out_mem   = out + (size_t)ND_ + 4;

    float *ln_tok, *cross, *big, *q, *k, *v, *ao, *eo, *retr, *outb, *upd, *pool, *gate;
    cudaGetSymbolAddress((void**)&ln_tok, g_ln_tok);
    cudaGetSymbolAddress((void**)&cross,  g_cross);
    cudaGetSymbolAddress((void**)&big,    g_big);
    cudaGetSymbolAddress((void**)&q,      g_q);
    cudaGetSymbolAddress((void**)&k,      g_k);
    cudaGetSymbolAddress((void**)&v,      g_v);
    cudaGetSymbolAddress((void**)&ao,     g_ao);
    cudaGetSymbolAddress((void**)&eo,     g_eo);
    cudaGetSymbolAddress((void**)&retr,   g_retr);
    cudaGetSymbolAddress((void**)&outb,   g_outb);
    cudaGetSymbolAddress((void**)&upd,    g_upd);
    cudaGetSymbolAddress((void**)&pool,   g_pool);
    cudaGetSymbolAddress((void**)&gate,   g_gate);
    float* h1 = big;

    const float rsD = 1.0f / sqrtf(512.f);

    ln_kernel<<<EN_, 128>>>(tokens, ln_tok);

    tc_gemm<1, false, true, false><<<g2(EN_, EN_, 1), 256>>>(
        EN_, EN_, D_, rsD, ln_tok, D_, 0, ln_tok, D_, 0, big, EN_, 0,
        nullptr, 0, nullptr, 0, N_);

    softmax_kernel<<<EN_, 256>>>(big, EN_);

    tc_gemm<5, false, false, false><<<g2(EN_, D_, 1), 256>>>(
        EN_, D_, EN_, 1.0f, big, EN_, 0, ln_tok, D_, 0, cross, D_, 0,
        nullptr, 0, ln_tok, 0, 0);

    {
        float* dst[3] = {q, k, v};
        for (int wsel = 0; wsel < 3; wsel++) {
            tc_gemm<3, false, true, false><<<g2(N_, D_, E_), 256>>>(
                N_, D_, D_, 1.0f,
                cross, D_, ND_,
                attn_wqkv + (size_t)wsel * DD_, D_, (size_t)3 * DD_,
                dst[wsel], D_, ND_,
                attn_bqkv + (size_t)wsel * D_, (size_t)3 * D_,
                nullptr, 0, 0);
        }
    }

    for (int e = 0; e < E_; e++) {
        tc_gemm<0, false, true, false><<<g2(N_, N_, 8), 256>>>(
            N_, N_, 64, 0.125f,
            q + (size_t)e * ND_, D_, 64,
            k + (size_t)e * ND_, D_, 64,
            big, N_, (size_t)NM_,
            nullptr, 0, nullptr, 0, 0);
        softmax_kernel<<<8 * N_, 256>>>(big, N_);
        tc_gemm<0, false, false, true><<<g2(N_, 64, 8), 256>>>(
            N_, 64, N_, 1.0f,
            big, N_, (size_t)NM_,
            v + (size_t)e * ND_, D_, 64,
            ao + (size_t)e * ND_, D_, 64,
            nullptr, 0, nullptr, 0, 0);
    }

    tc_gemm<3, false, true, false><<<g2(N_, D_, E_), 256>>>(
        N_, D_, D_, 1.0f, ao, D_, ND_, attn_wo, D_, DD_, q, D_, ND_,
        attn_bo, D_, nullptr, 0, 0);

    addln_kernel<<<EN_, 128>>>(cross, q, ln_g, ln_b, ao, 0);

    tc_gemm<4, false, true, false><<<g2(N_, F_, E_), 256>>>(
        N_, F_, D_, 1.0f, ao, D_, ND_, ffn_w1, D_, (size_t)F_ * D_, h1, F_, (size_t)N_ * F_,
        ffn_b1, F_, nullptr, 0, 0);

    tc_gemm<3, false, true, false><<<g2(N_, D_, E_), 256>>>(
        N_, D_, F_, 1.0f, h1, F_, (size_t)N_ * F_, ffn_w2, F_, (size_t)D_ * F_, q, D_, ND_,
        ffn_b2, D_, nullptr, 0, 0);

    addln_kernel<<<EN_, 128>>>(ao, q, ln_g, ln_b, eo, 1);

    for (int l = 0; l < L_; l++) {
        tc_gemm<2, false, true, false><<<g2(N_, M_, E_), 256>>>(
            N_, M_, D_, rsD,
            eo, D_, ND_,
            memories + (size_t)l * M_ * D_, D_, 0,
            big + (size_t)l * NM_, M_, (size_t)L_ * NM_,
            nullptr, 0, nullptr, 0, 0);
    }
    softmax_kernel<<<E_ * L_ * N_, 256>>>(big, M_);

    for (int l = 0; l < L_; l++) {
        tc_gemm<0, false, false, false><<<g2(N_, D_, E_), 256>>>(
            N_, D_, M_, 1.0f,
            big + (size_t)l * NM_, M_, (size_t)L_ * NM_,
            memories + (size_t)l * M_ * D_, D_, 0,
            retr + (size_t)l * D_, L_ * D_, (size_t)N_ * L_ * D_,
            nullptr, 0, nullptr, 0, 0);
    }

    zero_kernel<<<(L_ * M_ * D_ + 255) / 256, 256>>>(upd, (size_t)L_ * M_ * D_);
    for (int e = 0; e < E_; e++) {
        tc_gemm<6, true, false, false><<<g2(M_, D_, L_), 256>>>(
            M_, D_, N_, 1.0f,
            big + (size_t)e * L_ * NM_, M_, (size_t)NM_,
            eo + (size_t)e * ND_, D_, 0,
            upd, D_, (size_t)M_ * D_,
            nullptr, 0, nullptr, 0, 0);
    }

    newmem_kernel<<<(L_ * M_ * D_ + 255) / 256, 256>>>(memories, upd, out_mem, (size_t)L_ * M_ * D_);

    tc_gemm<5, false, true, false><<<g2(N_, D_, E_), 256>>>(
        N_, D_, L_ * D_, 1.0f,
        retr, L_ * D_, (size_t)N_ * L_ * D_,
        agg_w, L_ * D_, 0,
        outb, D_, ND_,
        agg_b, 0, eo, ND_, 0);

    pooled_kernel<<<dim3(2, E_), 256>>>(outb, pool);
    gate_kernel<<<1, 128>>>(pool, gate_w, gate, out_gate);
    fuse_kernel<<<(ND_ + 255) / 256, 256>>>(outb, gate, out_fused);

    (void)in_sizes; (void)n_in; (void)out_size;
}